// round 12
// baseline (speedup 1.0000x reference)
#include <cuda_runtime.h>
#include <cuda_bf16.h>
#include <math.h>

// Problem constants
#define BATCH 8
#define LSEQ 20
#define NN 2048
#define FF 64
#define NN2 (NN*NN)                 // 4194304
#define A_ELEMS ((size_t)BATCH*NN2) // 33554432

// Scratch (device globals; no allocation allowed)
__device__ __align__(16) float g_m2[BATCH*LSEQ*FF];
__device__ int      g_k[BATCH];
__device__ __align__(16) float g_xn [BATCH*NN*FF];    // x_norm (b,n,f)
__device__ __align__(16) float g_xnT[BATCH*FF*NN];    // A for GEMM1: [(b*64+f)][n]
__device__ __align__(16) float g_T  [BATCH*FF*NN];    // GEMM1 out:   [(b*64+f)][j]
__device__ __align__(16) unsigned g_hist1[BATCH*8192];
__device__ __align__(16) unsigned g_hist2[BATCH*524288];
__device__ unsigned g_h1[BATCH];
__device__ unsigned g_above1[BATCH];
__device__ unsigned g_thr[BATCH];
__device__ unsigned g_gt[BATCH];           // count of keys strictly > thr
__device__ unsigned g_tiecnt[BATCH];       // count of keys == thr
__device__ unsigned g_tieidx[BATCH*2048];  // flat indices of ties
__device__ unsigned g_cut[BATCH];          // exclusive index cutoff among ties

__device__ __forceinline__ unsigned tokey(float v) {
    unsigned u = __float_as_uint(v);
    return (u & 0x80000000u) ? ~u : (u | 0x80000000u);
}

// ---------------- zero scratch (graph replays!) ----------------
__global__ void k_zero() {
    size_t tid = (size_t)blockIdx.x * blockDim.x + threadIdx.x;
    size_t stride = (size_t)gridDim.x * blockDim.x;
    uint4 z = make_uint4(0u,0u,0u,0u);
    uint4* h1 = (uint4*)g_hist1;
    uint4* h2 = (uint4*)g_hist2;
    for (size_t i = tid; i < (BATCH*8192)/4; i += stride) h1[i] = z;
    for (size_t i = tid; i < (BATCH*524288)/4; i += stride) h2[i] = z;
    if (tid < BATCH) { g_tiecnt[tid] = 0u; g_gt[tid] = 0u; }
}

// ---------------- mean over N (XLA-CPU faithful): sequential f32 ascending n ----------------
__global__ void k_mean32(const float* __restrict__ x) {
    int bl = blockIdx.x;            // 0..159  => (b*20+l)
    int f  = threadIdx.x;           // 0..63
    const float* p = x + ((size_t)bl * NN) * FF + f;
    float s = 0.f;
    for (int n = 0; n < NN; n++) s = __fadd_rn(s, p[(size_t)n * FF]);
    g_m2[bl*FF + f] = __fdiv_rn(s, 2048.0f);
}

// ---- Eigen/XLA f32 fast tanh (generic_fast_tanh_float) ----
__device__ __forceinline__ float eigen_tanh_f32(float x) {
    const float c = 7.90531110763549805f;
    x = fminf(fmaxf(x, -c), c);
    if (fabsf(x) < 0.0004f) return x;
    float x2 = __fmul_rn(x, x);
    float p = -2.76076847742355e-16f;
    p = __fmaf_rn(x2, p,  2.00018790482477e-13f);
    p = __fmaf_rn(x2, p, -8.60467152213735e-11f);
    p = __fmaf_rn(x2, p,  5.12229709037114e-08f);
    p = __fmaf_rn(x2, p,  1.48572235717979e-05f);
    p = __fmaf_rn(x2, p,  6.37261928875436e-04f);
    p = __fmaf_rn(x2, p,  4.89352455891786e-03f);
    p = __fmul_rn(p, x);
    float q = 1.19825839466702e-06f;
    q = __fmaf_rn(x2, q, 1.18534705686654e-04f);
    q = __fmaf_rn(x2, q, 2.26843463243900e-03f);
    q = __fmaf_rn(x2, q, 4.89352518554385e-03f);
    return __fdiv_rn(p, q);
}

// exact gelu, fp32 rounding points like jax: x*(erf(x/sqrt2)+1)/2
__device__ __forceinline__ float gelu32(float x) {
    const float sqrt2 = 1.41421356237309504880f;  // rounds to f32 0x3FB504F3
    float e = erff(__fdiv_rn(x, sqrt2));
    return 0.5f * __fmul_rn(x, __fadd_rn(e, 1.0f));
}

// ---------------- conv head -> keep ratio -> k[b] (f32 faithful) ----------------
__global__ void k_head32(const float* __restrict__ w1, const float* __restrict__ b1,
                         const float* __restrict__ w2, const float* __restrict__ b2,
                         const float* __restrict__ w3, const float* __restrict__ b3,
                         const float* __restrict__ w4, const float* __restrict__ b4,
                         const float* __restrict__ wo, const float* __restrict__ bo) {
    int b = blockIdx.x;
    __shared__ float sm[22][66];   // zero-padded (H=20,W=64)
    __shared__ float feat[32];
    int j = threadIdx.x;           // 0..31: output channel
    // zero padding area + load
    for (int i = j; i < 22*66; i += 32) ((float*)sm)[i] = 0.f;
    __syncwarp();
    for (int i = j; i < LSEQ*FF; i += 32) {
        int h = i >> 6, w = i & 63;
        sm[h+1][w+1] = g_m2[(b*LSEQ + h)*FF + w];
    }
    __syncwarp();

    int g = j >> 3, cc = j & 7;
    float acc = 0.f;
    for (int i = 0; i < LSEQ*FF; i++) {   // sequential (h,w) ascending like XLA mean
        int h = i >> 6, w = i & 63;
        float y;
        if (g == 0) {
            y = __fadd_rn(__fmul_rn(w1[cc], sm[h+1][w+1]), b1[cc]);
        } else if (g == 1) {
            float s = __fmul_rn(w2[cc*3+0], sm[h+1][w]);
            s = __fmaf_rn(w2[cc*3+1], sm[h+1][w+1], s);
            s = __fmaf_rn(w2[cc*3+2], sm[h+1][w+2], s);
            y = __fadd_rn(s, b2[cc]);
        } else if (g == 2) {
            float s = __fmul_rn(w3[cc*3+0], sm[h][w+1]);
            s = __fmaf_rn(w3[cc*3+1], sm[h+1][w+1], s);
            s = __fmaf_rn(w3[cc*3+2], sm[h+2][w+1], s);
            y = __fadd_rn(s, b3[cc]);
        } else {
            const float* W = w4 + cc*9;
            float s = __fmul_rn(W[0], sm[h][w]);
            s = __fmaf_rn(W[1], sm[h][w+1], s);
            s = __fmaf_rn(W[2], sm[h][w+2], s);
            s = __fmaf_rn(W[3], sm[h+1][w], s);
            s = __fmaf_rn(W[4], sm[h+1][w+1], s);
            s = __fmaf_rn(W[5], sm[h+1][w+2], s);
            s = __fmaf_rn(W[6], sm[h+2][w], s);
            s = __fmaf_rn(W[7], sm[h+2][w+1], s);
            s = __fmaf_rn(W[8], sm[h+2][w+2], s);
            y = __fadd_rn(s, b4[cc]);
        }
        acc = __fadd_rn(acc, gelu32(y));
    }
    feat[j] = __fdiv_rn(acc, 1280.0f);
    __syncwarp();
    if (j == 0) {
        float lt = 0.f;
        #pragma unroll
        for (int jj = 0; jj < 32; jj++) lt = __fmaf_rn(feat[jj], wo[jj], lt);
        lt = __fadd_rn(lt, bo[0]);
        // XLA logistic expansion: 0.5 + 0.5*tanh(0.5*x), Eigen fast tanh
        float t = eigen_tanh_f32(__fmul_rn(0.5f, lt));
        float sg = __fadd_rn(0.5f, __fmul_rn(0.5f, t));
        float keep = fminf(fmaxf(__fmul_rn(0.2f, sg), 0.02f), 1.0f);
        float kf = ceilf(__fmul_rn(keep, 4194304.0f));
        int kk = (int)kf;
        g_k[b] = max(1, min(kk, NN2));
    }
}

// ---------------- normalize last slice (reference-faithful rounding chain) ----------------
__global__ void k_norm(const float* __restrict__ x) {
    int r = blockIdx.x * 256 + threadIdx.x;        // 0..16383 (row)
    if (r >= BATCH*NN) return;
    int b = r >> 11, n = r & 2047;
    const float* p = x + (((size_t)b*LSEQ + (LSEQ-1))*NN + n) * FF;
    float v[64];
    #pragma unroll
    for (int f = 0; f < 64; f++) v[f] = p[f];
    float s = 0.f;
    #pragma unroll
    for (int f = 0; f < 64; f++) {
        float sq = __fmul_rn(v[f], v[f]);   // separate rounded square (no FMA)
        s = __fadd_rn(s, sq);               // sequential fp32 sum
    }
    float nrm = sqrtf(s);
    float mx = fmaxf(nrm, 1e-12f);
    float* q = g_xn + (size_t)r * FF;
    #pragma unroll
    for (int f = 0; f < 64; f++) {
        float xv = __fdiv_rn(v[f], mx);
        q[f] = xv;
        g_xnT[((size_t)b*FF + f) * NN + n] = xv;
    }
}

// ---------------- compensated MAC: TwoSum + FMA-residual ----------------
__device__ __forceinline__ void cmac(float a, float b, float& hi, float& lo) {
    float p = a * b;
    float e = fmaf(a, b, -p);        // exact product residual
    float s = hi + p;
    float bb = s - hi;
    float err = (hi - (s - bb)) + (p - bb);   // TwoSum error
    hi = s;
    lo += err + e;
}

// ---------------- GEMM1 (compensated): g_T = g_xnT(512x2048) @ P(2048x2048) ----------------
__global__ void k_gemm1(const float* __restrict__ P) {
    __shared__ float As[16][68];
    __shared__ float Bs[16][64];
    int m0 = blockIdx.y * 64;
    int n0 = blockIdx.x * 64;
    int tid = threadIdx.x;
    int ty = tid >> 4, tx = tid & 15;
    float hi[4][4], lo[4][4];
    #pragma unroll
    for (int i=0;i<4;i++)
        #pragma unroll
        for (int jj=0;jj<4;jj++){ hi[i][jj]=0.f; lo[i][jj]=0.f; }

    int arow = tid >> 2;         // 0..63
    int acol = (tid & 3) * 4;    // 0..12
    int brow = tid >> 4;         // 0..15
    int bcol = (tid & 15) * 4;   // 0..60
    const float* Abase = g_xnT + (size_t)(m0 + arow) * NN + acol;
    const float* Bbase = P + (size_t)brow * NN + n0 + bcol;

    for (int k0 = 0; k0 < NN; k0 += 16) {
        float4 a4 = *(const float4*)(Abase + k0);
        float4 b4 = *(const float4*)(Bbase + (size_t)k0 * NN);
        As[acol+0][arow]=a4.x; As[acol+1][arow]=a4.y;
        As[acol+2][arow]=a4.z; As[acol+3][arow]=a4.w;
        *(float4*)&Bs[brow][bcol] = b4;
        __syncthreads();
        #pragma unroll
        for (int kk = 0; kk < 16; kk++) {
            float4 av = *(const float4*)&As[kk][ty*4];
            float4 bv = *(const float4*)&Bs[kk][tx*4];
            float a_[4] = {av.x, av.y, av.z, av.w};
            float b_[4] = {bv.x, bv.y, bv.z, bv.w};
            #pragma unroll
            for (int i = 0; i < 4; i++)
                #pragma unroll
                for (int jj = 0; jj < 4; jj++)
                    cmac(a_[i], b_[jj], hi[i][jj], lo[i][jj]);
        }
        __syncthreads();
    }
    #pragma unroll
    for (int i = 0; i < 4; i++) {
        float4 v = make_float4(hi[i][0]+lo[i][0], hi[i][1]+lo[i][1],
                               hi[i][2]+lo[i][2], hi[i][3]+lo[i][3]);
        *(float4*)(g_T + (size_t)(m0 + ty*4 + i) * NN + n0 + tx*4) = v;
    }
}

// ---------------- GEMM2: a[b] = g_xn[b](2048x64) @ g_T[b](64x2048) ----------------
__global__ void k_gemm2(float* __restrict__ aOut) {
    __shared__ float Xs[64][68];
    __shared__ float Ts[64][64];
    int b = blockIdx.z;
    int m0 = blockIdx.y * 64, n0 = blockIdx.x * 64;
    int tid = threadIdx.x;
    int ty = tid >> 4, tx = tid & 15;
    const float* X  = g_xn + (size_t)b * NN * FF;
    const float* Tm = g_T  + (size_t)b * FF * NN;
    int r  = tid >> 4;        // 0..15
    int c4 = (tid & 15) * 4;  // 0..60
    #pragma unroll
    for (int it = 0; it < 4; it++) {
        int row = r + it*16;
        float4 xv = *(const float4*)(X + (size_t)(m0+row)*FF + c4);
        Xs[c4+0][row]=xv.x; Xs[c4+1][row]=xv.y; Xs[c4+2][row]=xv.z; Xs[c4+3][row]=xv.w;
        float4 tv = *(const float4*)(Tm + (size_t)row*NN + n0 + c4);
        *(float4*)&Ts[row][c4] = tv;
    }
    __syncthreads();
    float acc[4][4];
    #pragma unroll
    for (int i=0;i<4;i++){ acc[i][0]=0;acc[i][1]=0;acc[i][2]=0;acc[i][3]=0; }
    #pragma unroll 8
    for (int k = 0; k < 64; k++) {
        float4 av = *(const float4*)&Xs[k][ty*4];
        float4 bv = *(const float4*)&Ts[k][tx*4];
        acc[0][0]+=av.x*bv.x; acc[0][1]+=av.x*bv.y; acc[0][2]+=av.x*bv.z; acc[0][3]+=av.x*bv.w;
        acc[1][0]+=av.y*bv.x; acc[1][1]+=av.y*bv.y; acc[1][2]+=av.y*bv.z; acc[1][3]+=av.y*bv.w;
        acc[2][0]+=av.z*bv.x; acc[2][1]+=av.z*bv.y; acc[2][2]+=av.z*bv.z; acc[2][3]+=av.z*bv.w;
        acc[3][0]+=av.w*bv.x; acc[3][1]+=av.w*bv.y; acc[3][2]+=av.w*bv.z; acc[3][3]+=av.w*bv.w;
    }
    #pragma unroll
    for (int i = 0; i < 4; i++) {
        float4 v = make_float4(acc[i][0], acc[i][1], acc[i][2], acc[i][3]);
        *(float4*)(aOut + ((size_t)b*NN + m0 + ty*4 + i) * NN + n0 + tx*4) = v;
    }
}

// ---------------- top-k select: pass 1 (8192 coarse bins, key>>19) ----------------
__global__ void k_hist1(const float* __restrict__ aOut) {
    __shared__ unsigned h[8192];
    int b = blockIdx.y;
    for (int i = threadIdx.x; i < 8192; i += 256) h[i] = 0;
    __syncthreads();
    const float4* p4 = (const float4*)(aOut + (size_t)b*NN2 + (size_t)blockIdx.x*131072);
    for (int i = threadIdx.x; i < 32768; i += 256) {
        float4 v = p4[i];
        atomicAdd(&h[tokey(v.x) >> 19], 1u);
        atomicAdd(&h[tokey(v.y) >> 19], 1u);
        atomicAdd(&h[tokey(v.z) >> 19], 1u);
        atomicAdd(&h[tokey(v.w) >> 19], 1u);
    }
    __syncthreads();
    for (int i = threadIdx.x; i < 8192; i += 256) {
        unsigned v = h[i];
        if (v) atomicAdd(&g_hist1[b*8192 + i], v);
    }
}

__global__ void k_sel1() {
    int b = blockIdx.x, t = threadIdx.x;
    __shared__ unsigned sm[256];
    __shared__ unsigned above[256];
    const unsigned* H = g_hist1 + b*8192;
    unsigned s = 0;
    for (int j = 0; j < 32; j++) s += H[t*32 + j];
    sm[t] = s;
    __syncthreads();
    if (t == 0) {
        unsigned run = 0;
        for (int i = 255; i >= 0; i--) { above[i] = run; run += sm[i]; }
    }
    __syncthreads();
    unsigned K = (unsigned)g_k[b];
    unsigned run = above[t];
    for (int j = 31; j >= 0; j--) {
        unsigned c = H[t*32 + j];
        if (run < K && K <= run + c) { g_h1[b] = (unsigned)(t*32 + j); g_above1[b] = run; }
        run += c;
    }
}

// ---------------- pass 2: exact low 19 bits within boundary bin ----------------
__global__ void k_hist2(const float* __restrict__ aOut) {
    int b = blockIdx.y;
    unsigned h1 = g_h1[b];
    unsigned* H = g_hist2 + (size_t)b * 524288;
    const float4* p4 = (const float4*)(aOut + (size_t)b*NN2 + (size_t)blockIdx.x*131072);
    for (int i = threadIdx.x; i < 32768; i += 256) {
        float4 v = p4[i];
        unsigned k0 = tokey(v.x), k1 = tokey(v.y), k2 = tokey(v.z), k3 = tokey(v.w);
        if ((k0 >> 19) == h1) atomicAdd(&H[k0 & 0x7FFFFu], 1u);
        if ((k1 >> 19) == h1) atomicAdd(&H[k1 & 0x7FFFFu], 1u);
        if ((k2 >> 19) == h1) atomicAdd(&H[k2 & 0x7FFFFu], 1u);
        if ((k3 >> 19) == h1) atomicAdd(&H[k3 & 0x7FFFFu], 1u);
    }
}

__global__ void k_sel2() {
    int b = blockIdx.x, t = threadIdx.x;
    __shared__ unsigned sm[256];
    __shared__ unsigned above[256];
    const unsigned* H = g_hist2 + (size_t)b * 524288;
    unsigned s = 0;
    for (int j = 0; j < 2048; j++) s += H[t*2048 + j];
    sm[t] = s;
    __syncthreads();
    if (t == 0) {
        unsigned run = 0;
        for (int i = 255; i >= 0; i--) { above[i] = run; run += sm[i]; }
    }
    __syncthreads();
    unsigned Kp = (unsigned)g_k[b] - g_above1[b];
    unsigned run = above[t];
    for (int j = 2047; j >= 0; j--) {
        unsigned c = H[t*2048 + j];
        if (run < Kp && Kp <= run + c)
            g_thr[b] = (g_h1[b] << 19) | (unsigned)(t*2048 + j);
        run += c;
    }
}

// ---------------- tie resolution: count > thr, collect == thr ----------------
__global__ void k_ties(const float* __restrict__ aOut) {
    int b = blockIdx.y;
    unsigned thr = g_thr[b];
    __shared__ unsigned s_gt;
    if (threadIdx.x == 0) s_gt = 0u;
    __syncthreads();
    unsigned base = (unsigned)blockIdx.x * 131072u;
    const float4* p4 = (const float4*)(aOut + (size_t)b*NN2 + base);
    unsigned loc = 0;
    for (int i = threadIdx.x; i < 32768; i += 256) {
        float4 v = p4[i];
        unsigned idx0 = base + (unsigned)i*4u;
        unsigned kk;
        kk = tokey(v.x);
        if (kk > thr) loc++;
        else if (kk == thr) { unsigned p = atomicAdd(&g_tiecnt[b],1u); if (p < 2048u) g_tieidx[b*2048+p] = idx0; }
        kk = tokey(v.y);
        if (kk > thr) loc++;
        else if (kk == thr) { unsigned p = atomicAdd(&g_tiecnt[b],1u); if (p < 2048u) g_tieidx[b*2048+p] = idx0+1u; }
        kk = tokey(v.z);
        if (kk > thr) loc++;
        else if (kk == thr) { unsigned p = atomicAdd(&g_tiecnt[b],1u); if (p < 2048u) g_tieidx[b*2048+p] = idx0+2u; }
        kk = tokey(v.w);
        if (kk > thr) loc++;
        else if (kk == thr) { unsigned p = atomicAdd(&g_tiecnt[b],1u); if (p < 2048u) g_tieidx[b*2048+p] = idx0+3u; }
    }
    atomicAdd(&s_gt, loc);
    __syncthreads();
    if (threadIdx.x == 0) atomicAdd(&g_gt[b], s_gt);
}

// m = k - gt ties to include, by ascending flat index (stable-argsort semantics)
__global__ void k_cut() {
    int b = blockIdx.x;
    unsigned K  = (unsigned)g_k[b];
    unsigned gt = g_gt[b];
    unsigned tc = g_tiecnt[b];
    __shared__ int mode;   // 0 = none, 1 = all, 2 = select
    int m = (int)K - (int)gt;
    if (threadIdx.x == 0) {
        if (m <= 0) { g_cut[b] = 0u; mode = 0; }
        else if ((unsigned)m >= tc || tc > 2048u) { g_cut[b] = 0xFFFFFFFFu; mode = 1; }
        else mode = 2;
    }
    __syncthreads();
    if (mode == 2) {
        const unsigned* buf = g_tieidx + b*2048;
        for (int i = threadIdx.x; i < (int)tc; i += blockDim.x) {
            unsigned v = buf[i];
            int cnt = 0;
            for (int jj = 0; jj < (int)tc; jj++) cnt += (buf[jj] < v) ? 1 : 0;
            if (cnt == m - 1) g_cut[b] = v + 1u;   // include indices < v+1
        }
    }
}

// ---------------- mask = (key > thr) | (key==thr & idx<cut) | diag ----------------
__global__ void k_mask(const float* __restrict__ aOut, float* __restrict__ mOut) {
    size_t i4 = (size_t)blockIdx.x * blockDim.x + threadIdx.x;   // float4 idx
    size_t base = i4 * 4;
    int b = (int)(base >> 22);
    unsigned thr = g_thr[b];
    unsigned cut = g_cut[b];
    float4 v = *(const float4*)(aOut + base);
    unsigned rem = (unsigned)(base & (NN2 - 1));
    unsigned row = rem >> 11, col = rem & 2047u;
    unsigned k0 = tokey(v.x), k1 = tokey(v.y), k2 = tokey(v.z), k3 = tokey(v.w);
    float4 m;
    m.x = (k0 > thr || (k0 == thr && rem      < cut) || row == col    ) ? 1.0f : 0.0f;
    m.y = (k1 > thr || (k1 == thr && rem + 1u < cut) || row == col + 1) ? 1.0f : 0.0f;
    m.z = (k2 > thr || (k2 == thr && rem + 2u < cut) || row == col + 2) ? 1.0f : 0.0f;
    m.w = (k3 > thr || (k3 == thr && rem + 3u < cut) || row == col + 3) ? 1.0f : 0.0f;
    *(float4*)(mOut + base) = m;
}

extern "C" void kernel_launch(void* const* d_in, const int* in_sizes, int n_in,
                              void* d_out, int out_size) {
    const float* x     = (const float*)d_in[0];
    const float* prior = (const float*)d_in[1];
    const float* w1 = (const float*)d_in[2];
    const float* b1 = (const float*)d_in[3];
    const float* w2 = (const float*)d_in[4];
    const float* b2 = (const float*)d_in[5];
    const float* w3 = (const float*)d_in[6];
    const float* b3 = (const float*)d_in[7];
    const float* w4 = (const float*)d_in[8];
    const float* b4 = (const float*)d_in[9];
    const float* wo = (const float*)d_in[10];
    const float* bo = (const float*)d_in[11];

    float* out  = (float*)d_out;          // [mask (33554432) | a (33554432)]
    float* aOut = out + A_ELEMS;

    k_zero<<<1024, 256>>>();
    k_mean32<<<BATCH*LSEQ, 64>>>(x);
    k_head32<<<BATCH, 32>>>(w1,b1,w2,b2,w3,b3,w4,b4,wo,bo);
    k_norm<<<64, 256>>>(x);
    k_gemm1<<<dim3(NN/64, (BATCH*FF)/64), 256>>>(prior);
    k_gemm2<<<dim3(NN/64, NN/64, BATCH), 256>>>(aOut);
    k_hist1<<<dim3(32, BATCH), 256>>>(aOut);
    k_sel1<<<BATCH, 256>>>();
    k_hist2<<<dim3(32, BATCH), 256>>>(aOut);
    k_sel2<<<BATCH, 256>>>();
    k_ties<<<dim3(32, BATCH), 256>>>(aOut);
    k_cut<<<BATCH, 256>>>();
    k_mask<<<32768, 256>>>(aOut, out);
}

// round 13
// speedup vs baseline: 1.3377x; 1.3377x over previous
#include <cuda_runtime.h>
#include <cuda_bf16.h>
#include <math.h>

// Problem constants
#define BATCH 8
#define LSEQ 20
#define NN 2048
#define FF 64
#define NN2 (NN*NN)                 // 4194304
#define A_ELEMS ((size_t)BATCH*NN2) // 33554432

typedef unsigned long long ull;

// Scratch (device globals; no allocation allowed)
__device__ __align__(16) float g_m2[BATCH*LSEQ*FF];
__device__ int      g_k[BATCH];
__device__ __align__(16) float g_xn [BATCH*NN*FF];    // x_norm (b,n,f)
__device__ __align__(16) float g_xnT[BATCH*FF*NN];    // A for GEMM1: [(b*64+f)][n]
__device__ __align__(16) float g_T  [BATCH*FF*NN];    // GEMM1 out:   [(b*64+f)][j]
__device__ __align__(16) unsigned g_hist1[BATCH*8192];
__device__ __align__(16) unsigned g_hist2[BATCH*524288];
__device__ unsigned g_h1[BATCH];
__device__ unsigned g_above1[BATCH];
__device__ unsigned g_thr[BATCH];
__device__ unsigned g_gt[BATCH];           // count of keys strictly > thr
__device__ unsigned g_tiecnt[BATCH];       // count of keys == thr
__device__ unsigned g_tieidx[BATCH*2048];  // flat indices of ties
__device__ unsigned g_cut[BATCH];          // exclusive index cutoff among ties

__device__ __forceinline__ unsigned tokey(float v) {
    unsigned u = __float_as_uint(v);
    return (u & 0x80000000u) ? ~u : (u | 0x80000000u);
}

// ---- packed f32x2 helpers (Blackwell dual-lane fp32; PTX-only) ----
__device__ __forceinline__ ull pack2(float lo, float hi) {
    ull r; asm("mov.b64 %0, {%1, %2};" : "=l"(r) : "f"(lo), "f"(hi)); return r;
}
__device__ __forceinline__ void unpack2(ull v, float& lo, float& hi) {
    asm("mov.b64 {%0, %1}, %2;" : "=f"(lo), "=f"(hi) : "l"(v));
}
__device__ __forceinline__ ull fma_x2(ull a, ull b, ull c) {
    ull r; asm("fma.rn.f32x2 %0, %1, %2, %3;" : "=l"(r) : "l"(a), "l"(b), "l"(c)); return r;
}
__device__ __forceinline__ ull add_x2(ull a, ull b) {
    ull r; asm("add.rn.f32x2 %0, %1, %2;" : "=l"(r) : "l"(a), "l"(b)); return r;
}
__device__ __forceinline__ ull mul_x2(ull a, ull b) {
    ull r; asm("mul.rn.f32x2 %0, %1, %2;" : "=l"(r) : "l"(a), "l"(b)); return r;
}
#define NEG1X2 0xBF800000BF800000ULL

// ---------------- zero scratch (graph replays!) ----------------
__global__ void k_zero() {
    size_t tid = (size_t)blockIdx.x * blockDim.x + threadIdx.x;
    size_t stride = (size_t)gridDim.x * blockDim.x;
    uint4 z = make_uint4(0u,0u,0u,0u);
    uint4* h1 = (uint4*)g_hist1;
    uint4* h2 = (uint4*)g_hist2;
    for (size_t i = tid; i < (BATCH*8192)/4; i += stride) h1[i] = z;
    for (size_t i = tid; i < (BATCH*524288)/4; i += stride) h2[i] = z;
    if (tid < BATCH) { g_tiecnt[tid] = 0u; g_gt[tid] = 0u; }
}

// ---------------- mean over N (XLA-CPU faithful): sequential f32 ascending n ----------------
__global__ void k_mean32(const float* __restrict__ x) {
    int bl = blockIdx.x;            // 0..159  => (b*20+l)
    int f  = threadIdx.x;           // 0..63
    const float* p = x + ((size_t)bl * NN) * FF + f;
    float s = 0.f;
    for (int n = 0; n < NN; n++) s = __fadd_rn(s, p[(size_t)n * FF]);
    g_m2[bl*FF + f] = __fdiv_rn(s, 2048.0f);
}

// ---- Eigen/XLA f32 fast tanh (generic_fast_tanh_float) ----
__device__ __forceinline__ float eigen_tanh_f32(float x) {
    const float c = 7.90531110763549805f;
    x = fminf(fmaxf(x, -c), c);
    if (fabsf(x) < 0.0004f) return x;
    float x2 = __fmul_rn(x, x);
    float p = -2.76076847742355e-16f;
    p = __fmaf_rn(x2, p,  2.00018790482477e-13f);
    p = __fmaf_rn(x2, p, -8.60467152213735e-11f);
    p = __fmaf_rn(x2, p,  5.12229709037114e-08f);
    p = __fmaf_rn(x2, p,  1.48572235717979e-05f);
    p = __fmaf_rn(x2, p,  6.37261928875436e-04f);
    p = __fmaf_rn(x2, p,  4.89352455891786e-03f);
    p = __fmul_rn(p, x);
    float q = 1.19825839466702e-06f;
    q = __fmaf_rn(x2, q, 1.18534705686654e-04f);
    q = __fmaf_rn(x2, q, 2.26843463243900e-03f);
    q = __fmaf_rn(x2, q, 4.89352518554385e-03f);
    return __fdiv_rn(p, q);
}

// exact gelu, fp32 rounding points like jax: x*(erf(x/sqrt2)+1)/2
__device__ __forceinline__ float gelu32(float x) {
    const float sqrt2 = 1.41421356237309504880f;
    float e = erff(__fdiv_rn(x, sqrt2));
    return 0.5f * __fmul_rn(x, __fadd_rn(e, 1.0f));
}

// ---------------- conv head -> keep ratio -> k[b] (f32 faithful) ----------------
__global__ void k_head32(const float* __restrict__ w1, const float* __restrict__ b1,
                         const float* __restrict__ w2, const float* __restrict__ b2,
                         const float* __restrict__ w3, const float* __restrict__ b3,
                         const float* __restrict__ w4, const float* __restrict__ b4,
                         const float* __restrict__ wo, const float* __restrict__ bo) {
    int b = blockIdx.x;
    __shared__ float sm[22][66];   // zero-padded (H=20,W=64)
    __shared__ float feat[32];
    int j = threadIdx.x;           // 0..31: output channel
    for (int i = j; i < 22*66; i += 32) ((float*)sm)[i] = 0.f;
    __syncwarp();
    for (int i = j; i < LSEQ*FF; i += 32) {
        int h = i >> 6, w = i & 63;
        sm[h+1][w+1] = g_m2[(b*LSEQ + h)*FF + w];
    }
    __syncwarp();

    int g = j >> 3, cc = j & 7;
    float acc = 0.f;
    for (int i = 0; i < LSEQ*FF; i++) {   // sequential (h,w) ascending like XLA mean
        int h = i >> 6, w = i & 63;
        float y;
        if (g == 0) {
            y = __fadd_rn(__fmul_rn(w1[cc], sm[h+1][w+1]), b1[cc]);
        } else if (g == 1) {
            float s = __fmul_rn(w2[cc*3+0], sm[h+1][w]);
            s = __fmaf_rn(w2[cc*3+1], sm[h+1][w+1], s);
            s = __fmaf_rn(w2[cc*3+2], sm[h+1][w+2], s);
            y = __fadd_rn(s, b2[cc]);
        } else if (g == 2) {
            float s = __fmul_rn(w3[cc*3+0], sm[h][w+1]);
            s = __fmaf_rn(w3[cc*3+1], sm[h+1][w+1], s);
            s = __fmaf_rn(w3[cc*3+2], sm[h+2][w+1], s);
            y = __fadd_rn(s, b3[cc]);
        } else {
            const float* W = w4 + cc*9;
            float s = __fmul_rn(W[0], sm[h][w]);
            s = __fmaf_rn(W[1], sm[h][w+1], s);
            s = __fmaf_rn(W[2], sm[h][w+2], s);
            s = __fmaf_rn(W[3], sm[h+1][w], s);
            s = __fmaf_rn(W[4], sm[h+1][w+1], s);
            s = __fmaf_rn(W[5], sm[h+1][w+2], s);
            s = __fmaf_rn(W[6], sm[h+2][w], s);
            s = __fmaf_rn(W[7], sm[h+2][w+1], s);
            s = __fmaf_rn(W[8], sm[h+2][w+2], s);
            y = __fadd_rn(s, b4[cc]);
        }
        acc = __fadd_rn(acc, gelu32(y));
    }
    feat[j] = __fdiv_rn(acc, 1280.0f);
    __syncwarp();
    if (j == 0) {
        float lt = 0.f;
        #pragma unroll
        for (int jj = 0; jj < 32; jj++) lt = __fmaf_rn(feat[jj], wo[jj], lt);
        lt = __fadd_rn(lt, bo[0]);
        float t = eigen_tanh_f32(__fmul_rn(0.5f, lt));
        float sg = __fadd_rn(0.5f, __fmul_rn(0.5f, t));
        float keep = fminf(fmaxf(__fmul_rn(0.2f, sg), 0.02f), 1.0f);
        float kf = ceilf(__fmul_rn(keep, 4194304.0f));
        int kk = (int)kf;
        g_k[b] = max(1, min(kk, NN2));
    }
}

// ---------------- normalize last slice (reference-faithful rounding chain) ----------------
__global__ void k_norm(const float* __restrict__ x) {
    int r = blockIdx.x * 256 + threadIdx.x;        // 0..16383 (row)
    if (r >= BATCH*NN) return;
    int b = r >> 11, n = r & 2047;
    const float* p = x + (((size_t)b*LSEQ + (LSEQ-1))*NN + n) * FF;
    float v[64];
    #pragma unroll
    for (int f = 0; f < 64; f++) v[f] = p[f];
    float s = 0.f;
    #pragma unroll
    for (int f = 0; f < 64; f++) {
        float sq = __fmul_rn(v[f], v[f]);   // separate rounded square (no FMA)
        s = __fadd_rn(s, sq);               // sequential fp32 sum
    }
    float nrm = sqrtf(s);
    float mx = fmaxf(nrm, 1e-12f);
    float* q = g_xn + (size_t)r * FF;
    #pragma unroll
    for (int f = 0; f < 64; f++) {
        float xv = __fdiv_rn(v[f], mx);
        q[f] = xv;
        g_xnT[((size_t)b*FF + f) * NN + n] = xv;
    }
}

// ---------------- GEMM1 (Kahan, f32x2): g_T = g_xnT(512x2048) @ P(2048x2048) ----------------
// Kahan with FMA-folded product: y=fma(a,b,nc); t=s+y; nc=(s-t)+y; s=t.  (nc = -c)
// Error O(eps) independent of K => effectively exact, same as previous TwoSum version.
__global__ void k_gemm1(const float* __restrict__ P) {
    __shared__ float As[16][68];
    __shared__ float Bs[16][64];
    int m0 = blockIdx.y * 64;
    int n0 = blockIdx.x * 64;
    int tid = threadIdx.x;
    int ty = tid >> 4, tx = tid & 15;
    ull s[4][2], nc[4][2];
    #pragma unroll
    for (int i=0;i<4;i++)
        #pragma unroll
        for (int p2=0;p2<2;p2++){ s[i][p2]=0ULL; nc[i][p2]=0ULL; }

    int arow = tid >> 2;         // 0..63
    int acol = (tid & 3) * 4;    // 0..12
    int brow = tid >> 4;         // 0..15
    int bcol = (tid & 15) * 4;   // 0..60
    const float* Abase = g_xnT + (size_t)(m0 + arow) * NN + acol;
    const float* Bbase = P + (size_t)brow * NN + n0 + bcol;
    const ull M1 = NEG1X2;

    for (int k0 = 0; k0 < NN; k0 += 16) {
        float4 a4 = *(const float4*)(Abase + k0);
        float4 b4 = *(const float4*)(Bbase + (size_t)k0 * NN);
        As[acol+0][arow]=a4.x; As[acol+1][arow]=a4.y;
        As[acol+2][arow]=a4.z; As[acol+3][arow]=a4.w;
        *(float4*)&Bs[brow][bcol] = b4;
        __syncthreads();
        #pragma unroll
        for (int kk = 0; kk < 16; kk++) {
            float4 av = *(const float4*)&As[kk][ty*4];
            const ull* bp = (const ull*)&Bs[kk][tx*4];
            ull b0 = bp[0], b1 = bp[1];
            float a_[4] = {av.x, av.y, av.z, av.w};
            #pragma unroll
            for (int i = 0; i < 4; i++) {
                ull aa = pack2(a_[i], a_[i]);
                // pair 0 (cols tx*4+0, tx*4+1)
                {
                    ull y = fma_x2(aa, b0, nc[i][0]);
                    ull t = add_x2(s[i][0], y);
                    ull nt = mul_x2(t, M1);
                    ull u = add_x2(s[i][0], nt);
                    nc[i][0] = add_x2(u, y);
                    s[i][0] = t;
                }
                // pair 1 (cols tx*4+2, tx*4+3)
                {
                    ull y = fma_x2(aa, b1, nc[i][1]);
                    ull t = add_x2(s[i][1], y);
                    ull nt = mul_x2(t, M1);
                    ull u = add_x2(s[i][1], nt);
                    nc[i][1] = add_x2(u, y);
                    s[i][1] = t;
                }
            }
        }
        __syncthreads();
    }
    #pragma unroll
    for (int i = 0; i < 4; i++) {
        float s0,s1,s2,s3, c0,c1,c2,c3;
        unpack2(s[i][0], s0, s1);  unpack2(s[i][1], s2, s3);
        unpack2(nc[i][0], c0, c1); unpack2(nc[i][1], c2, c3);
        // final estimate = s - c = s + nc
        float4 v = make_float4(s0 + c0, s1 + c1, s2 + c2, s3 + c3);
        *(float4*)(g_T + (size_t)(m0 + ty*4 + i) * NN + n0 + tx*4) = v;
    }
}

// ---------------- GEMM2 (f32x2, bit-identical to scalar ascending-k FFMA chain) ----------------
__global__ void k_gemm2(float* __restrict__ aOut) {
    __shared__ float Xs[64][68];
    __shared__ float Ts[64][64];
    int b = blockIdx.z;
    int m0 = blockIdx.y * 64, n0 = blockIdx.x * 64;
    int tid = threadIdx.x;
    int ty = tid >> 4, tx = tid & 15;
    const float* X  = g_xn + (size_t)b * NN * FF;
    const float* Tm = g_T  + (size_t)b * FF * NN;
    int r  = tid >> 4;        // 0..15
    int c4 = (tid & 15) * 4;  // 0..60
    #pragma unroll
    for (int it = 0; it < 4; it++) {
        int row = r + it*16;
        float4 xv = *(const float4*)(X + (size_t)(m0+row)*FF + c4);
        Xs[c4+0][row]=xv.x; Xs[c4+1][row]=xv.y; Xs[c4+2][row]=xv.z; Xs[c4+3][row]=xv.w;
        float4 tv = *(const float4*)(Tm + (size_t)row*NN + n0 + c4);
        *(float4*)&Ts[row][c4] = tv;
    }
    __syncthreads();
    ull acc[4][2];
    #pragma unroll
    for (int i=0;i<4;i++){ acc[i][0]=0ULL; acc[i][1]=0ULL; }
    #pragma unroll 8
    for (int k = 0; k < 64; k++) {
        float4 av = *(const float4*)&Xs[k][ty*4];
        const ull* bp = (const ull*)&Ts[k][tx*4];
        ull b0 = bp[0], b1 = bp[1];
        float a_[4] = {av.x, av.y, av.z, av.w};
        #pragma unroll
        for (int i = 0; i < 4; i++) {
            ull aa = pack2(a_[i], a_[i]);
            acc[i][0] = fma_x2(aa, b0, acc[i][0]);
            acc[i][1] = fma_x2(aa, b1, acc[i][1]);
        }
    }
    #pragma unroll
    for (int i = 0; i < 4; i++) {
        float v0,v1,v2,v3;
        unpack2(acc[i][0], v0, v1);
        unpack2(acc[i][1], v2, v3);
        float4 v = make_float4(v0, v1, v2, v3);
        *(float4*)(aOut + ((size_t)b*NN + m0 + ty*4 + i) * NN + n0 + tx*4) = v;
    }
}

// ---------------- top-k select: pass 1 (8192 coarse bins, key>>19) ----------------
__global__ void k_hist1(const float* __restrict__ aOut) {
    __shared__ unsigned h[8192];
    int b = blockIdx.y;
    for (int i = threadIdx.x; i < 8192; i += 256) h[i] = 0;
    __syncthreads();
    const float4* p4 = (const float4*)(aOut + (size_t)b*NN2 + (size_t)blockIdx.x*131072);
    for (int i = threadIdx.x; i < 32768; i += 256) {
        float4 v = p4[i];
        atomicAdd(&h[tokey(v.x) >> 19], 1u);
        atomicAdd(&h[tokey(v.y) >> 19], 1u);
        atomicAdd(&h[tokey(v.z) >> 19], 1u);
        atomicAdd(&h[tokey(v.w) >> 19], 1u);
    }
    __syncthreads();
    for (int i = threadIdx.x; i < 8192; i += 256) {
        unsigned v = h[i];
        if (v) atomicAdd(&g_hist1[b*8192 + i], v);
    }
}

__global__ void k_sel1() {
    int b = blockIdx.x, t = threadIdx.x;
    __shared__ unsigned sm[256];
    __shared__ unsigned above[256];
    const unsigned* H = g_hist1 + b*8192;
    unsigned s = 0;
    for (int j = 0; j < 32; j++) s += H[t*32 + j];
    sm[t] = s;
    __syncthreads();
    if (t == 0) {
        unsigned run = 0;
        for (int i = 255; i >= 0; i--) { above[i] = run; run += sm[i]; }
    }
    __syncthreads();
    unsigned K = (unsigned)g_k[b];
    unsigned run = above[t];
    for (int j = 31; j >= 0; j--) {
        unsigned c = H[t*32 + j];
        if (run < K && K <= run + c) { g_h1[b] = (unsigned)(t*32 + j); g_above1[b] = run; }
        run += c;
    }
}

// ---------------- pass 2: exact low 19 bits within boundary bin ----------------
__global__ void k_hist2(const float* __restrict__ aOut) {
    int b = blockIdx.y;
    unsigned h1 = g_h1[b];
    unsigned* H = g_hist2 + (size_t)b * 524288;
    const float4* p4 = (const float4*)(aOut + (size_t)b*NN2 + (size_t)blockIdx.x*131072);
    for (int i = threadIdx.x; i < 32768; i += 256) {
        float4 v = p4[i];
        unsigned k0 = tokey(v.x), k1 = tokey(v.y), k2 = tokey(v.z), k3 = tokey(v.w);
        if ((k0 >> 19) == h1) atomicAdd(&H[k0 & 0x7FFFFu], 1u);
        if ((k1 >> 19) == h1) atomicAdd(&H[k1 & 0x7FFFFu], 1u);
        if ((k2 >> 19) == h1) atomicAdd(&H[k2 & 0x7FFFFu], 1u);
        if ((k3 >> 19) == h1) atomicAdd(&H[k3 & 0x7FFFFu], 1u);
    }
}

__global__ void k_sel2() {
    int b = blockIdx.x, t = threadIdx.x;
    __shared__ unsigned sm[256];
    __shared__ unsigned above[256];
    const unsigned* H = g_hist2 + (size_t)b * 524288;
    unsigned s = 0;
    for (int j = 0; j < 2048; j++) s += H[t*2048 + j];
    sm[t] = s;
    __syncthreads();
    if (t == 0) {
        unsigned run = 0;
        for (int i = 255; i >= 0; i--) { above[i] = run; run += sm[i]; }
    }
    __syncthreads();
    unsigned Kp = (unsigned)g_k[b] - g_above1[b];
    unsigned run = above[t];
    for (int j = 2047; j >= 0; j--) {
        unsigned c = H[t*2048 + j];
        if (run < Kp && Kp <= run + c)
            g_thr[b] = (g_h1[b] << 19) | (unsigned)(t*2048 + j);
        run += c;
    }
}

// ---------------- tie resolution: count > thr, collect == thr ----------------
__global__ void k_ties(const float* __restrict__ aOut) {
    int b = blockIdx.y;
    unsigned thr = g_thr[b];
    __shared__ unsigned s_gt;
    if (threadIdx.x == 0) s_gt = 0u;
    __syncthreads();
    unsigned base = (unsigned)blockIdx.x * 131072u;
    const float4* p4 = (const float4*)(aOut + (size_t)b*NN2 + base);
    unsigned loc = 0;
    for (int i = threadIdx.x; i < 32768; i += 256) {
        float4 v = p4[i];
        unsigned idx0 = base + (unsigned)i*4u;
        unsigned kk;
        kk = tokey(v.x);
        if (kk > thr) loc++;
        else if (kk == thr) { unsigned p = atomicAdd(&g_tiecnt[b],1u); if (p < 2048u) g_tieidx[b*2048+p] = idx0; }
        kk = tokey(v.y);
        if (kk > thr) loc++;
        else if (kk == thr) { unsigned p = atomicAdd(&g_tiecnt[b],1u); if (p < 2048u) g_tieidx[b*2048+p] = idx0+1u; }
        kk = tokey(v.z);
        if (kk > thr) loc++;
        else if (kk == thr) { unsigned p = atomicAdd(&g_tiecnt[b],1u); if (p < 2048u) g_tieidx[b*2048+p] = idx0+2u; }
        kk = tokey(v.w);
        if (kk > thr) loc++;
        else if (kk == thr) { unsigned p = atomicAdd(&g_tiecnt[b],1u); if (p < 2048u) g_tieidx[b*2048+p] = idx0+3u; }
    }
    atomicAdd(&s_gt, loc);
    __syncthreads();
    if (threadIdx.x == 0) atomicAdd(&g_gt[b], s_gt);
}

// m = k - gt ties to include, by ascending flat index (stable-argsort semantics)
__global__ void k_cut() {
    int b = blockIdx.x;
    unsigned K  = (unsigned)g_k[b];
    unsigned gt = g_gt[b];
    unsigned tc = g_tiecnt[b];
    __shared__ int mode;   // 0 = none, 1 = all, 2 = select
    int m = (int)K - (int)gt;
    if (threadIdx.x == 0) {
        if (m <= 0) { g_cut[b] = 0u; mode = 0; }
        else if ((unsigned)m >= tc || tc > 2048u) { g_cut[b] = 0xFFFFFFFFu; mode = 1; }
        else mode = 2;
    }
    __syncthreads();
    if (mode == 2) {
        const unsigned* buf = g_tieidx + b*2048;
        for (int i = threadIdx.x; i < (int)tc; i += blockDim.x) {
            unsigned v = buf[i];
            int cnt = 0;
            for (int jj = 0; jj < (int)tc; jj++) cnt += (buf[jj] < v) ? 1 : 0;
            if (cnt == m - 1) g_cut[b] = v + 1u;   // include indices < v+1
        }
    }
}

// ---------------- mask = (key > thr) | (key==thr & idx<cut) | diag ----------------
__global__ void k_mask(const float* __restrict__ aOut, float* __restrict__ mOut) {
    size_t i4 = (size_t)blockIdx.x * blockDim.x + threadIdx.x;   // float4 idx
    size_t base = i4 * 4;
    int b = (int)(base >> 22);
    unsigned thr = g_thr[b];
    unsigned cut = g_cut[b];
    float4 v = *(const float4*)(aOut + base);
    unsigned rem = (unsigned)(base & (NN2 - 1));
    unsigned row = rem >> 11, col = rem & 2047u;
    unsigned k0 = tokey(v.x), k1 = tokey(v.y), k2 = tokey(v.z), k3 = tokey(v.w);
    float4 m;
    m.x = (k0 > thr || (k0 == thr && rem      < cut) || row == col    ) ? 1.0f : 0.0f;
    m.y = (k1 > thr || (k1 == thr && rem + 1u < cut) || row == col + 1) ? 1.0f : 0.0f;
    m.z = (k2 > thr || (k2 == thr && rem + 2u < cut) || row == col + 2) ? 1.0f : 0.0f;
    m.w = (k3 > thr || (k3 == thr && rem + 3u < cut) || row == col + 3) ? 1.0f : 0.0f;
    *(float4*)(mOut + base) = m;
}

extern "C" void kernel_launch(void* const* d_in, const int* in_sizes, int n_in,
                              void* d_out, int out_size) {
    const float* x     = (const float*)d_in[0];
    const float* prior = (const float*)d_in[1];
    const float* w1 = (const float*)d_in[2];
    const float* b1 = (const float*)d_in[3];
    const float* w2 = (const float*)d_in[4];
    const float* b2 = (const float*)d_in[5];
    const float* w3 = (const float*)d_in[6];
    const float* b3 = (const float*)d_in[7];
    const float* w4 = (const float*)d_in[8];
    const float* b4 = (const float*)d_in[9];
    const float* wo = (const float*)d_in[10];
    const float* bo = (const float*)d_in[11];

    float* out  = (float*)d_out;          // [mask (33554432) | a (33554432)]
    float* aOut = out + A_ELEMS;

    k_zero<<<1024, 256>>>();
    k_mean32<<<BATCH*LSEQ, 64>>>(x);
    k_head32<<<BATCH, 32>>>(w1,b1,w2,b2,w3,b3,w4,b4,wo,bo);
    k_norm<<<64, 256>>>(x);
    k_gemm1<<<dim3(NN/64, (BATCH*FF)/64), 256>>>(prior);
    k_gemm2<<<dim3(NN/64, NN/64, BATCH), 256>>>(aOut);
    k_hist1<<<dim3(32, BATCH), 256>>>(aOut);
    k_sel1<<<BATCH, 256>>>();
    k_hist2<<<dim3(32, BATCH), 256>>>(aOut);
    k_sel2<<<BATCH, 256>>>();
    k_ties<<<dim3(32, BATCH), 256>>>(aOut);
    k_cut<<<BATCH, 256>>>();
    k_mask<<<32768, 256>>>(aOut, out);
}